// round 2
// baseline (speedup 1.0000x reference)
#include <cuda_runtime.h>
#include <cstdint>

#define KK 16
#define BB 512
#define NP 4096
#define VV 32
#define EPSF 1e-13f
#define TOLF 1.001e-5f   // np.isclose to 1.0: rtol(1e-5)*1 + atol(1e-8)

// packed labels: byte k of element n = c_in[n][k] (all < 32)
__device__ uint4 g_c8[NP];

__global__ void pack_labels_kernel(const int* __restrict__ c_in) {
    int t = blockIdx.x * blockDim.x + threadIdx.x;
    if (t < NP) {
        const int4* p = (const int4*)(c_in + t * KK);
        int4 a = p[0], b = p[1], c = p[2], d = p[3];
        uint4 r;
        r.x = (a.x & 255u) | ((a.y & 255u) << 8) | ((a.z & 255u) << 16) | ((a.w & 255u) << 24);
        r.y = (b.x & 255u) | ((b.y & 255u) << 8) | ((b.z & 255u) << 16) | ((b.w & 255u) << 24);
        r.z = (c.x & 255u) | ((c.y & 255u) << 8) | ((c.z & 255u) << 16) | ((c.w & 255u) << 24);
        r.w = (d.x & 255u) | ((d.y & 255u) << 8) | ((d.z & 255u) << 16) | ((d.w & 255u) << 24);
        g_c8[t] = r;
    }
}

__global__ __launch_bounds__(512, 3) void beran_kernel(
    const float* __restrict__ delta,
    const float* __restrict__ c_p,
    const float* __restrict__ bwp,
    float* __restrict__ out)
{
    __shared__ float s_score[KK * 32];  // 2 KB
    __shared__ float ws[16];
    __shared__ float wb[16];            // warp-boundary surv values
    __shared__ float s_tot_sh, s2_tot_sh;

    const int tid  = threadIdx.x;
    const int lane = tid & 31;
    const int wid  = tid >> 5;          // 0..15
    const int b    = blockIdx.x;
    const unsigned FULL = 0xFFFFFFFFu;

    // ---- Phase A: softmax + score table. warp wid handles concept k=wid ----
    {
        float x = c_p[(wid * BB + b) * VV + lane];
        float m = x;
        #pragma unroll
        for (int d = 16; d; d >>= 1) m = fmaxf(m, __shfl_xor_sync(FULL, m, d));
        float e = __expf(x - m);
        float s = e;
        #pragma unroll
        for (int d = 16; d; d >>= 1) s += __shfl_xor_sync(FULL, s, d);
        float p = e / s;
        float ssq = p * p;
        #pragma unroll
        for (int d = 16; d; d >>= 1) ssq += __shfl_xor_sync(FULL, ssq, d);
        s_score[wid * 32 + lane] = ssq - 2.0f * p + 1.0f;   // score[k][v]
    }
    __syncthreads();

    // lane caches score[k][v=lane] for all k
    float sreg[KK];
    #pragma unroll
    for (int k = 0; k < KK; k++) sreg[k] = s_score[k * 32 + lane];

    const float bw = fminf(fmaxf(bwp[0], 0.1f), 10.0f);
    const float nib = -1.0f / bw;
    const int base = tid * 8;

    // ---- Phase B: metric via register-shuffle gather, DIRECT layout ----
    // thread t owns n = 8t..8t+7, so w stays in registers for the scan.
    float o[8];
    #pragma unroll
    for (int j = 0; j < 8; j++) {
        uint4 pk = g_c8[base + j];
        float m = 0.0f;
        #pragma unroll
        for (int k = 0; k < 4; k++) m += __shfl_sync(FULL, sreg[k],      (pk.x >> (8 * k)) & 31);
        #pragma unroll
        for (int k = 0; k < 4; k++) m += __shfl_sync(FULL, sreg[4 + k],  (pk.y >> (8 * k)) & 31);
        #pragma unroll
        for (int k = 0; k < 4; k++) m += __shfl_sync(FULL, sreg[8 + k],  (pk.z >> (8 * k)) & 31);
        #pragma unroll
        for (int k = 0; k < 4; k++) m += __shfl_sync(FULL, sreg[12 + k], (pk.w >> (8 * k)) & 31);
        o[j] = __expf(m * nib);
    }

    // ---- Phase C: scan #1 (cumsum of w) ----
    float cw[8];
    cw[0] = o[0];
    #pragma unroll
    for (int j = 1; j < 8; j++) cw[j] = cw[j - 1] + o[j];

    float tot = cw[7];
    float ti = tot;
    #pragma unroll
    for (int d = 1; d < 32; d <<= 1) {
        float u = __shfl_up_sync(FULL, ti, d);
        if (lane >= d) ti += u;
    }
    if (lane == 31) ws[wid] = ti;
    __syncthreads();
    if (wid == 0) {
        float v = (lane < 16) ? ws[lane] : 0.0f;
        float vi = v;
        #pragma unroll
        for (int d = 1; d < 16; d <<= 1) {
            float u = __shfl_up_sync(FULL, vi, d);
            if (lane >= d) vi += u;
        }
        if (lane < 16) ws[lane] = vi - v;      // exclusive warp-prefix
        if (lane == 15) s_tot_sh = vi;         // grand total
    }
    __syncthreads();

    const float off1 = ws[wid] + (ti - tot);   // exclusive prefix for this thread
    const float s_tot = s_tot_sh;
    const float inv_s = (s_tot < EPSF) ? 0.0f : 1.0f / s_tot;

    // ---- Phase D: xi = log((1-shifted)/(1-wc)), fused single fast log ----
    float dl[8];
    {
        const float4* dp = (const float4*)(delta + base);
        float4 d0 = dp[0], d1 = dp[1];
        dl[0] = d0.x; dl[1] = d0.y; dl[2] = d0.z; dl[3] = d0.w;
        dl[4] = d1.x; dl[5] = d1.y; dl[6] = d1.z; dl[7] = d1.w;
    }
    float hz[8];
    #pragma unroll
    for (int j = 0; j < 8; j++) {
        float wc = (cw[j] + off1) * inv_s;     // normalized inclusive cumsum
        float Wn = o[j] * inv_s;               // normalized weight
        float sh = wc - Wn;                    // shifted, exact reference rounding
        float t1 = 1.0f - wc;
        float t2 = 1.0f - sh;
        bool bad = (fabsf(t2) <= TOLF) || (fabsf(t1) <= TOLF);
        float xi = bad ? 0.0f : __logf(__fdividef(t2, t1));
        hz[j] = dl[j] * xi;
    }

    // ---- Phase E: scan #2 (cumsum of delta*xi) ----
    #pragma unroll
    for (int j = 1; j < 8; j++) hz[j] += hz[j - 1];
    float tot2 = hz[7];
    float ti2 = tot2;
    #pragma unroll
    for (int d = 1; d < 32; d <<= 1) {
        float u = __shfl_up_sync(FULL, ti2, d);
        if (lane >= d) ti2 += u;
    }
    __syncthreads();   // protect ws reuse (off1 reads done)
    if (lane == 31) ws[wid] = ti2;
    __syncthreads();
    if (wid == 0) {
        float v = (lane < 16) ? ws[lane] : 0.0f;
        float vi = v;
        #pragma unroll
        for (int d = 1; d < 16; d <<= 1) {
            float u = __shfl_up_sync(FULL, vi, d);
            if (lane >= d) vi += u;
        }
        if (lane < 16) ws[lane] = vi - v;
    }
    __syncthreads();
    const float off2 = ws[wid] + (ti2 - tot2);

    float surv[8];
    #pragma unroll
    for (int j = 0; j < 8; j++) surv[j] = __expf(-(hz[j] + off2));

    // write surv_func
    {
        float4* op = (float4*)(out + (size_t)b * NP + base);
        op[0] = make_float4(surv[0], surv[1], surv[2], surv[3]);
        op[1] = make_float4(surv[4], surv[5], surv[6], surv[7]);
    }
    if (lane == 31) wb[wid] = surv[7];
    __syncthreads();

    // ---- Phase F: surv_steps ----
    float prev = __shfl_up_sync(FULL, surv[7], 1);
    if (lane == 0) prev = (wid == 0) ? 1.0f : wb[wid - 1];
    if (tid == 0) prev = 1.0f;

    float st[8];
    float loc = 0.0f;
    #pragma unroll
    for (int j = 0; j < 8; j++) {
        st[j] = prev - surv[j];
        prev = surv[j];
        loc += st[j];
    }
    #pragma unroll
    for (int d = 16; d; d >>= 1) loc += __shfl_xor_sync(FULL, loc, d);
    if (lane == 0) ws[wid] = loc;
    __syncthreads();
    if (wid == 0) {
        float v = (lane < 16) ? ws[lane] : 0.0f;
        #pragma unroll
        for (int d = 8; d; d >>= 1) v += __shfl_xor_sync(FULL, v, d);
        if (lane == 0) s2_tot_sh = v;
    }
    __syncthreads();
    const float s2 = s2_tot_sh;
    const float inv2 = (s2 < EPSF) ? 0.0f : 1.0f / s2;

    {
        float4* op = (float4*)(out + (size_t)BB * NP + (size_t)b * NP + base);
        op[0] = make_float4(st[0] * inv2, st[1] * inv2, st[2] * inv2, st[3] * inv2);
        op[1] = make_float4(st[4] * inv2, st[5] * inv2, st[6] * inv2, st[7] * inv2);
    }
}

extern "C" void kernel_launch(void* const* d_in, const int* in_sizes, int n_in,
                              void* d_out, int out_size) {
    const int*   c_in  = (const int*)d_in[0];
    const float* delta = (const float*)d_in[1];
    const float* c_p   = (const float*)d_in[2];
    const float* bwp   = (const float*)d_in[3];
    float* out = (float*)d_out;

    pack_labels_kernel<<<16, 256>>>(c_in);
    beran_kernel<<<BB, 512>>>(delta, c_p, bwp, out);
}

// round 3
// speedup vs baseline: 1.2912x; 1.2912x over previous
#include <cuda_runtime.h>
#include <cstdint>

#define KK 16
#define BB 512
#define NP 4096
#define VV 32
#define EPSF 1e-13f
#define TOLF 1.001e-5f   // np.isclose to 1.0: rtol(1e-5)*1.0 + atol(1e-8)

// packed labels: byte k of element n = c_in[n][k] (all < 32)
__device__ uint4 g_c8[NP];

__global__ void pack_labels_kernel(const int* __restrict__ c_in) {
    int t = blockIdx.x * blockDim.x + threadIdx.x;
    if (t < NP) {
        const int4* p = (const int4*)(c_in + t * KK);
        int4 a = p[0], b = p[1], c = p[2], d = p[3];
        uint4 r;
        r.x = (a.x & 255u) | ((a.y & 255u) << 8) | ((a.z & 255u) << 16) | ((a.w & 255u) << 24);
        r.y = (b.x & 255u) | ((b.y & 255u) << 8) | ((b.z & 255u) << 16) | ((b.w & 255u) << 24);
        r.z = (c.x & 255u) | ((c.y & 255u) << 8) | ((c.z & 255u) << 16) | ((c.w & 255u) << 24);
        r.w = (d.x & 255u) | ((d.y & 255u) << 8) | ((d.z & 255u) << 16) | ((d.w & 255u) << 24);
        g_c8[t] = r;
    }
}

__global__ __launch_bounds__(512, 3) void beran_kernel(
    const float* __restrict__ delta,
    const float* __restrict__ c_p,
    const float* __restrict__ bwp,
    float* __restrict__ out)
{
    __shared__ float w_sh[NP];          // 16 KB staging: w in n-order
    __shared__ float s_score[KK * 32];  // 2 KB
    __shared__ float ws[16];
    __shared__ float wb[16];            // warp-boundary surv values
    __shared__ float s_tot_sh, s2_tot_sh;

    const int tid  = threadIdx.x;
    const int lane = tid & 31;
    const int wid  = tid >> 5;          // 0..15
    const int b    = blockIdx.x;
    const unsigned FULL = 0xFFFFFFFFu;

    // ---- Phase A: softmax + score table. warp wid handles concept k=wid ----
    {
        float x = c_p[(wid * BB + b) * VV + lane];
        float m = x;
        #pragma unroll
        for (int d = 16; d; d >>= 1) m = fmaxf(m, __shfl_xor_sync(FULL, m, d));
        float e = __expf(x - m);
        float s = e;
        #pragma unroll
        for (int d = 16; d; d >>= 1) s += __shfl_xor_sync(FULL, s, d);
        float p = __fdividef(e, s);
        float ssq = p * p;
        #pragma unroll
        for (int d = 16; d; d >>= 1) ssq += __shfl_xor_sync(FULL, ssq, d);
        s_score[wid * 32 + lane] = ssq - 2.0f * p + 1.0f;   // score[k][v]
    }
    __syncthreads();

    // lane caches score[k][v=lane] for all k
    float sreg[KK];
    #pragma unroll
    for (int k = 0; k < KK; k++) sreg[k] = s_score[k * 32 + lane];

    const float bw = fminf(fmaxf(bwp[0], 0.1f), 10.0f);
    const float nib = -1.0f / bw;

    // ---- Phase B: COALESCED gather (n = wid*256 + ci*32 + lane) → w_sh ----
    #pragma unroll
    for (int ci = 0; ci < 8; ci++) {
        int n = (wid * 8 + ci) * 32 + lane;
        uint4 pk = g_c8[n];
        float m = 0.0f;
        #pragma unroll
        for (int k = 0; k < 4; k++) m += __shfl_sync(FULL, sreg[k],      (pk.x >> (8 * k)) & 31);
        #pragma unroll
        for (int k = 0; k < 4; k++) m += __shfl_sync(FULL, sreg[4 + k],  (pk.y >> (8 * k)) & 31);
        #pragma unroll
        for (int k = 0; k < 4; k++) m += __shfl_sync(FULL, sreg[8 + k],  (pk.z >> (8 * k)) & 31);
        #pragma unroll
        for (int k = 0; k < 4; k++) m += __shfl_sync(FULL, sreg[12 + k], (pk.w >> (8 * k)) & 31);
        w_sh[n] = __expf(m * nib);
    }
    __syncthreads();

    // ---- Phase C: scan #1 (cumsum of w), 8 contiguous elems per thread ----
    const int base = tid * 8;
    float o[8], cw[8];
    {
        float4 a0 = ((const float4*)w_sh)[tid * 2];
        float4 a1 = ((const float4*)w_sh)[tid * 2 + 1];
        o[0] = a0.x; o[1] = a0.y; o[2] = a0.z; o[3] = a0.w;
        o[4] = a1.x; o[5] = a1.y; o[6] = a1.z; o[7] = a1.w;
    }
    cw[0] = o[0];
    #pragma unroll
    for (int j = 1; j < 8; j++) cw[j] = cw[j - 1] + o[j];

    float tot = cw[7];
    float ti = tot;
    #pragma unroll
    for (int d = 1; d < 32; d <<= 1) {
        float u = __shfl_up_sync(FULL, ti, d);
        if (lane >= d) ti += u;
    }
    if (lane == 31) ws[wid] = ti;
    __syncthreads();
    if (wid == 0) {
        float v = (lane < 16) ? ws[lane] : 0.0f;
        float vi = v;
        #pragma unroll
        for (int d = 1; d < 16; d <<= 1) {
            float u = __shfl_up_sync(FULL, vi, d);
            if (lane >= d) vi += u;
        }
        if (lane < 16) ws[lane] = vi - v;      // exclusive warp-prefix
        if (lane == 15) s_tot_sh = vi;         // grand total
    }
    __syncthreads();

    const float off1 = ws[wid] + (ti - tot);   // exclusive prefix for this thread
    const float s_tot = s_tot_sh;
    const float inv_s = (s_tot < EPSF) ? 0.0f : 1.0f / s_tot;

    // ---- Phase D: xi = log((1-shifted)/(1-wc)), single fused fast log ----
    float dl[8];
    {
        const float4* dp = (const float4*)(delta + base);
        float4 d0 = dp[0], d1 = dp[1];
        dl[0] = d0.x; dl[1] = d0.y; dl[2] = d0.z; dl[3] = d0.w;
        dl[4] = d1.x; dl[5] = d1.y; dl[6] = d1.z; dl[7] = d1.w;
    }
    float hz[8];
    #pragma unroll
    for (int j = 0; j < 8; j++) {
        float wc = (cw[j] + off1) * inv_s;     // normalized inclusive cumsum
        float Wn = o[j] * inv_s;               // normalized weight
        float sh = wc - Wn;                    // shifted, reference rounding
        float t1 = 1.0f - wc;
        float t2 = 1.0f - sh;
        bool bad = (fabsf(t2) <= TOLF) || (fabsf(t1) <= TOLF);
        float xi = bad ? 0.0f : __logf(__fdividef(t2, t1));
        hz[j] = dl[j] * xi;
    }

    // ---- Phase E: scan #2 (cumsum of delta*xi) ----
    #pragma unroll
    for (int j = 1; j < 8; j++) hz[j] += hz[j - 1];
    float tot2 = hz[7];
    float ti2 = tot2;
    #pragma unroll
    for (int d = 1; d < 32; d <<= 1) {
        float u = __shfl_up_sync(FULL, ti2, d);
        if (lane >= d) ti2 += u;
    }
    __syncthreads();   // off1 reads done before ws reuse
    if (lane == 31) ws[wid] = ti2;
    __syncthreads();
    if (wid == 0) {
        float v = (lane < 16) ? ws[lane] : 0.0f;
        float vi = v;
        #pragma unroll
        for (int d = 1; d < 16; d <<= 1) {
            float u = __shfl_up_sync(FULL, vi, d);
            if (lane >= d) vi += u;
        }
        if (lane < 16) ws[lane] = vi - v;
    }
    __syncthreads();
    const float off2 = ws[wid] + (ti2 - tot2);

    float surv[8];
    #pragma unroll
    for (int j = 0; j < 8; j++) surv[j] = __expf(-(hz[j] + off2));

    // write surv_func
    {
        float4* op = (float4*)(out + (size_t)b * NP + base);
        op[0] = make_float4(surv[0], surv[1], surv[2], surv[3]);
        op[1] = make_float4(surv[4], surv[5], surv[6], surv[7]);
    }
    if (lane == 31) wb[wid] = surv[7];
    __syncthreads();

    // ---- Phase F: surv_steps ----
    float prev = __shfl_up_sync(FULL, surv[7], 1);
    if (lane == 0) prev = (wid == 0) ? 1.0f : wb[wid - 1];
    if (tid == 0) prev = 1.0f;

    float st[8];
    float loc = 0.0f;
    #pragma unroll
    for (int j = 0; j < 8; j++) {
        st[j] = prev - surv[j];
        prev = surv[j];
        loc += st[j];
    }
    #pragma unroll
    for (int d = 16; d; d >>= 1) loc += __shfl_xor_sync(FULL, loc, d);
    if (lane == 0) ws[wid] = loc;
    __syncthreads();
    if (wid == 0) {
        float v = (lane < 16) ? ws[lane] : 0.0f;
        #pragma unroll
        for (int d = 8; d; d >>= 1) v += __shfl_xor_sync(FULL, v, d);
        if (lane == 0) s2_tot_sh = v;
    }
    __syncthreads();
    const float s2 = s2_tot_sh;
    const float inv2 = (s2 < EPSF) ? 0.0f : 1.0f / s2;

    {
        float4* op = (float4*)(out + (size_t)BB * NP + (size_t)b * NP + base);
        op[0] = make_float4(st[0] * inv2, st[1] * inv2, st[2] * inv2, st[3] * inv2);
        op[1] = make_float4(st[4] * inv2, st[5] * inv2, st[6] * inv2, st[7] * inv2);
    }
}

extern "C" void kernel_launch(void* const* d_in, const int* in_sizes, int n_in,
                              void* d_out, int out_size) {
    const int*   c_in  = (const int*)d_in[0];
    const float* delta = (const float*)d_in[1];
    const float* c_p   = (const float*)d_in[2];
    const float* bwp   = (const float*)d_in[3];
    float* out = (float*)d_out;

    pack_labels_kernel<<<16, 256>>>(c_in);
    beran_kernel<<<BB, 512>>>(delta, c_p, bwp, out);
}